// round 2
// baseline (speedup 1.0000x reference)
#include <cuda_runtime.h>
#include <math.h>

#define HN 5
#define PP 50
#define BB 2048
#define NTOT (BB*PP)
#define NEDGEF 5120000.0f
#define EPSBN 1e-5f
#define BPB 5            // batches per block
#define TPB 256          // 250 active threads (one per dst node)
#define NBLK ((BB + BPB - 1) / BPB)
#define TWO_PI 6.283185307179586f

// ---- scratch (no allocations allowed: __device__ globals) ----
__device__ float g_acc1[10];   // sum(a1[c]), sum(a1[c]^2)
__device__ float g_acc2[20];   // sum(h1[c]), sum(h1[a]*h1[b]) upper-tri (15)
__device__ float g_F1[25];     // folded layer1: FAfi, Fb1, FAfj, FW13, FW14 (5 each)
__device__ float g_W2f[25];    // BN2-folded W2
__device__ float g_b2f[HN];    // BN2-folded b2

__global__ void k_init() {
    int t = threadIdx.x;
    if (t < 10) g_acc1[t] = 0.0f;
    if (t < 20) g_acc2[t] = 0.0f;
}

// ---------------- pass 1: stats of a1 = mlp_in @ W1^T + b1 over all edges ----------------
__global__ __launch_bounds__(TPB) void k_pass1(
    const float* __restrict__ features, const float* __restrict__ angles,
    const float* __restrict__ W1, const float* __restrict__ b1)
{
    __shared__ float4 s_node[BPB * PP];  // {f, u, v, -} per node
    __shared__ float s_blk[10];
    const int t = threadIdx.x;
    if (t < 10) s_blk[t] = 0.0f;
    const int g = t / PP;
    const int i = t - g * PP;
    const int batch = blockIdx.x * BPB + g;
    const bool active = (t < BPB * PP) && (batch < BB);
    float fi = 0.f, ar = 0.f, ai = 0.f;
    if (active) {
        int node = batch * PP + i;
        fi = features[node];
        float2 an = ((const float2*)angles)[node];
        ar = an.x; ai = an.y;
        float inv = 1.0f / (ar*ar + ai*ai);
        s_node[t] = make_float4(fi, ar*inv, ai*inv, 0.f);
    }
    __syncthreads();

    float sa[HN], ssa[HN];
#pragma unroll
    for (int c = 0; c < HN; c++) { sa[c] = 0.f; ssa[c] = 0.f; }

    if (active) {
        float tt[HN], Afj[HN], pc[HN], qc[HN];
#pragma unroll
        for (int c = 0; c < HN; c++) {
            float w0 = __ldg(&W1[c*5+0]), w1 = __ldg(&W1[c*5+1]), w2 = __ldg(&W1[c*5+2]);
            float w3 = __ldg(&W1[c*5+3]), w4 = __ldg(&W1[c*5+4]);
            Afj[c] = w1 + w2;
            tt[c]  = fmaf(w0 - w2, fi, __ldg(&b1[c]));
            pc[c]  = w3*ar + w4*ai;
            qc[c]  = w3*ai - w4*ar;
        }
        const int base = g * PP;
#pragma unroll 5
        for (int j = 0; j < PP; j++) {
            float4 nj = s_node[base + j];
#pragma unroll
            for (int c = 0; c < HN; c++) {
                float a = fmaf(Afj[c], nj.x, tt[c]);
                a = fmaf(pc[c], nj.y, a);
                a = fmaf(qc[c], nj.z, a);
                sa[c] += a;
                ssa[c] = fmaf(a, a, ssa[c]);
            }
        }
    }
#pragma unroll
    for (int c = 0; c < HN; c++) {
#pragma unroll
        for (int o = 16; o > 0; o >>= 1) {
            sa[c]  += __shfl_down_sync(0xffffffffu, sa[c],  o);
            ssa[c] += __shfl_down_sync(0xffffffffu, ssa[c], o);
        }
    }
    if ((t & 31) == 0) {
#pragma unroll
        for (int c = 0; c < HN; c++) {
            atomicAdd(&s_blk[c],      sa[c]);
            atomicAdd(&s_blk[HN + c], ssa[c]);
        }
    }
    __syncthreads();
    if (t < 10) atomicAdd(&g_acc1[t], s_blk[t]);
}

// ---------------- finalize 1: fold BN1 into layer-1 coefficients ----------------
__global__ void k_fin1(const float* __restrict__ W1, const float* __restrict__ b1,
                       const float* __restrict__ g1, const float* __restrict__ bt1)
{
    int c = threadIdx.x;
    if (c < HN) {
        const float invE = 1.0f / NEDGEF;
        float mean = g_acc1[c] * invE;
        float var  = g_acc1[5 + c] * invE - mean * mean;
        float s1 = g1[c] * rsqrtf(var + EPSBN);
        float o1 = bt1[c] - mean * s1;
        float w0 = W1[c*5+0], w1 = W1[c*5+1], w2 = W1[c*5+2], w3 = W1[c*5+3], w4 = W1[c*5+4];
        g_F1[c]      = s1 * (w0 - w2);        // FAfi
        g_F1[5 + c]  = fmaf(s1, b1[c], o1);   // Fb1
        g_F1[10 + c] = s1 * (w1 + w2);        // FAfj
        g_F1[15 + c] = s1 * w3;               // FW13
        g_F1[20 + c] = s1 * w4;               // FW14
    }
}

// ---------------- pass 2: h1 moments (layer-2 stats factor through them) ----------------
__global__ __launch_bounds__(TPB) void k_pass2(
    const float* __restrict__ features, const float* __restrict__ angles)
{
    __shared__ float4 s_node[BPB * PP];
    __shared__ float s_blk[20];
    const int t = threadIdx.x;
    if (t < 20) s_blk[t] = 0.0f;
    const int g = t / PP;
    const int i = t - g * PP;
    const int batch = blockIdx.x * BPB + g;
    const bool active = (t < BPB * PP) && (batch < BB);
    float fi = 0.f, ar = 0.f, ai = 0.f;
    if (active) {
        int node = batch * PP + i;
        fi = features[node];
        float2 an = ((const float2*)angles)[node];
        ar = an.x; ai = an.y;
        float inv = 1.0f / (ar*ar + ai*ai);
        s_node[t] = make_float4(fi, ar*inv, ai*inv, 0.f);
    }
    __syncthreads();

    float m1a[HN], M2a[15];
#pragma unroll
    for (int c = 0; c < HN; c++) m1a[c] = 0.f;
#pragma unroll
    for (int c = 0; c < 15; c++) M2a[c] = 0.f;

    if (active) {
        float th[HN], Afj[HN], pc[HN], qc[HN];
#pragma unroll
        for (int c = 0; c < HN; c++) {
            float F0 = g_F1[c], Fb = g_F1[5+c], F2 = g_F1[10+c], F3 = g_F1[15+c], F4 = g_F1[20+c];
            Afj[c] = F2;
            th[c]  = fmaf(F0, fi, Fb);
            pc[c]  = F3*ar + F4*ai;
            qc[c]  = F3*ai - F4*ar;
        }
        const int base = g * PP;
#pragma unroll 2
        for (int j = 0; j < PP; j++) {
            float4 nj = s_node[base + j];
            float h1[HN];
#pragma unroll
            for (int c = 0; c < HN; c++) {
                float a = fmaf(Afj[c], nj.x, th[c]);
                a = fmaf(pc[c], nj.y, a);
                a = fmaf(qc[c], nj.z, a);
                h1[c] = fmaxf(a, 0.01f * a);    // leaky relu
                m1a[c] += h1[c];
            }
            int idx = 0;
#pragma unroll
            for (int a2 = 0; a2 < HN; a2++)
#pragma unroll
                for (int b2 = a2; b2 < HN; b2++) {
                    M2a[idx] = fmaf(h1[a2], h1[b2], M2a[idx]);
                    idx++;
                }
        }
    }
    // reduce 20 values
#pragma unroll
    for (int c = 0; c < HN; c++)
#pragma unroll
        for (int o = 16; o > 0; o >>= 1)
            m1a[c] += __shfl_down_sync(0xffffffffu, m1a[c], o);
#pragma unroll
    for (int c = 0; c < 15; c++)
#pragma unroll
        for (int o = 16; o > 0; o >>= 1)
            M2a[c] += __shfl_down_sync(0xffffffffu, M2a[c], o);
    if ((t & 31) == 0) {
#pragma unroll
        for (int c = 0; c < HN; c++) atomicAdd(&s_blk[c], m1a[c]);
#pragma unroll
        for (int c = 0; c < 15; c++) atomicAdd(&s_blk[HN + c], M2a[c]);
    }
    __syncthreads();
    if (t < 20) atomicAdd(&g_acc2[t], s_blk[t]);
}

// ---------------- finalize 2: analytic layer-2 stats, fold BN2 into W2 ----------------
__global__ void k_fin2(const float* __restrict__ W2, const float* __restrict__ b2,
                       const float* __restrict__ g2, const float* __restrict__ bt2)
{
    int c = threadIdx.x;
    if (c < HN) {
        const float invE = 1.0f / NEDGEF;
        float w[HN], m1[HN];
#pragma unroll
        for (int k = 0; k < HN; k++) { w[k] = W2[c*5+k]; m1[k] = g_acc2[k] * invE; }
        float Sm = 0.f;
#pragma unroll
        for (int k = 0; k < HN; k++) Sm = fmaf(w[k], m1[k], Sm);
        float Sq = 0.f;
        int idx = 0;
#pragma unroll
        for (int a = 0; a < HN; a++)
#pragma unroll
            for (int b = a; b < HN; b++) {
                float m = g_acc2[5 + idx] * invE;
                float term = w[a] * w[b] * m;
                Sq += (a == b) ? term : 2.0f * term;
                idx++;
            }
        float bc   = b2[c];
        float mean = Sm + bc;
        float ex2  = Sq + bc * (2.0f * Sm + bc);
        float var  = ex2 - mean * mean;
        float s2 = g2[c] * rsqrtf(var + EPSBN);
        float o2 = bt2[c] - mean * s2;
#pragma unroll
        for (int k = 0; k < HN; k++) g_W2f[c*5+k] = s2 * w[k];
        g_b2f[c] = fmaf(s2, bc, o2);
    }
}

// ---------------- pass 3: full forward + aggregation + output ----------------
__global__ __launch_bounds__(TPB) void k_pass3(
    const float* __restrict__ pt, const float* __restrict__ features,
    const float* __restrict__ angles, const float* __restrict__ W3,
    const float* __restrict__ b3, float* __restrict__ out)
{
    __shared__ float4 s_node[BPB * PP];
    const int t = threadIdx.x;
    const int g = t / PP;
    const int i = t - g * PP;
    const int batch = blockIdx.x * BPB + g;
    const bool active = (t < BPB * PP) && (batch < BB);
    float fi = 0.f, ar = 0.f, ai = 0.f;
    int node = 0;
    if (active) {
        node = batch * PP + i;
        fi = features[node];
        float2 an = ((const float2*)angles)[node];
        ar = an.x; ai = an.y;
        float inv = 1.0f / (ar*ar + ai*ai);
        s_node[t] = make_float4(fi, ar*inv, ai*inv, 0.f);
    }
    __syncthreads();
    if (!active) return;

    float th[HN], Afj[HN], pc[HN], qc[HN];
#pragma unroll
    for (int c = 0; c < HN; c++) {
        float F0 = g_F1[c], Fb = g_F1[5+c], F2 = g_F1[10+c], F3 = g_F1[15+c], F4 = g_F1[20+c];
        Afj[c] = F2;
        th[c]  = fmaf(F0, fi, Fb);
        pc[c]  = F3*ar + F4*ai;
        qc[c]  = F3*ai - F4*ar;
    }
    float W2f[25], b2f[HN];
#pragma unroll
    for (int c = 0; c < 25; c++) W2f[c] = g_W2f[c];
#pragma unroll
    for (int c = 0; c < HN; c++) b2f[c] = g_b2f[c];

    float Sh2[HN];
#pragma unroll
    for (int c = 0; c < HN; c++) Sh2[c] = 0.f;

    const int base = g * PP;
#pragma unroll 2
    for (int j = 0; j < PP; j++) {
        float4 nj = s_node[base + j];
        float h1[HN];
#pragma unroll
        for (int c = 0; c < HN; c++) {
            float a = fmaf(Afj[c], nj.x, th[c]);
            a = fmaf(pc[c], nj.y, a);
            a = fmaf(qc[c], nj.z, a);
            h1[c] = fmaxf(a, 0.01f * a);
        }
#pragma unroll
        for (int c = 0; c < HN; c++) {
            float a2 = b2f[c];
#pragma unroll
            for (int k = 0; k < HN; k++) a2 = fmaf(W2f[c*5+k], h1[k], a2);
            float h2 = fmaxf(a2, 0.01f * a2);
            Sh2[c] += h2;
        }
    }
    // layer 3 applied once to the summed h2 (linear => commutes with sum)
    float sn[HN];
#pragma unroll
    for (int c = 0; c < HN; c++) sn[c] = Sh2[c] * (1.0f / (float)PP);
    float m[HN];
#pragma unroll
    for (int kk = 0; kk < HN; kk++) {
        float acc = __ldg(&b3[kk]);
#pragma unroll
        for (int k = 0; k < HN; k++) acc = fmaf(__ldg(&W3[kk*5+k]), sn[k], acc);
        m[kk] = acc;
    }
    float si, cs;
    sincosf(TWO_PI * m[4], &si, &cs);
    float* o = out + (size_t)node * 7;
    o[0] = pt[node];
    o[1] = m[0];
    o[2] = m[1];
    o[3] = m[2];
    o[4] = m[3];
    o[5] = cs * ar - si * ai;
    o[6] = cs * ai + si * ar;
}

extern "C" void kernel_launch(void* const* d_in, const int* in_sizes, int n_in,
                              void* d_out, int out_size)
{
    const float* pt       = (const float*)d_in[0];
    const float* features = (const float*)d_in[1];
    const float* angles   = (const float*)d_in[2];
    const float* W1       = (const float*)d_in[3];
    const float* b1       = (const float*)d_in[4];
    const float* g1       = (const float*)d_in[5];
    const float* bt1      = (const float*)d_in[6];
    const float* W2       = (const float*)d_in[7];
    const float* b2       = (const float*)d_in[8];
    const float* g2       = (const float*)d_in[9];
    const float* bt2      = (const float*)d_in[10];
    const float* W3       = (const float*)d_in[11];
    const float* b3       = (const float*)d_in[12];
    // d_in[13] = edge_index: structure is analytic (dense per-batch clique,
    // dst-major meshgrid), so it is not needed.
    float* out = (float*)d_out;

    k_init<<<1, 32>>>();
    k_pass1<<<NBLK, TPB>>>(features, angles, W1, b1);
    k_fin1<<<1, 32>>>(W1, b1, g1, bt1);
    k_pass2<<<NBLK, TPB>>>(features, angles);
    k_fin2<<<1, 32>>>(W2, b2, g2, bt2);
    k_pass3<<<NBLK, TPB>>>(pt, features, angles, W3, b3, out);
}

// round 3
// speedup vs baseline: 1.0007x; 1.0007x over previous
#include <cuda_runtime.h>
#include <math.h>

#define HN 5
#define PP 50
#define BB 2048
#define NTOT (BB*PP)
#define NEDGEF 5120000.0f
#define EPSBN 1e-5f
#define BPB 5            // batches per block
#define TPB 256          // 250 active threads (one per dst node)
#define NBLK ((BB + BPB - 1) / BPB)
#define TWO_PI 6.283185307179586f

// ---- scratch (no allocations allowed: __device__ globals) ----
__device__ float g_acc1[10];   // sum(a1[c]), sum(a1[c]^2)
__device__ float g_acc2[20];   // sum(h1[c]), sum(h1[a]*h1[b]) upper-tri (15)
__device__ float g_F1[25];     // folded layer1: FAfi, Fb1, FAfj, FW13, FW14 (5 each)
__device__ float g_W2f[25];    // BN2-folded W2
__device__ float g_b2f[HN];    // BN2-folded b2

__global__ void k_init() {
    int t = threadIdx.x;
    if (t < 10) g_acc1[t] = 0.0f;
    if (t < 20) g_acc2[t] = 0.0f;
}

// ---------------- pass 1: stats of a1 = mlp_in @ W1^T + b1 over all edges ----------------
__global__ __launch_bounds__(TPB) void k_pass1(
    const float* __restrict__ features, const float* __restrict__ angles,
    const float* __restrict__ W1, const float* __restrict__ b1)
{
    __shared__ float4 s_node[BPB * PP];  // {f, u, v, -} per node
    __shared__ float s_blk[10];
    const int t = threadIdx.x;
    if (t < 10) s_blk[t] = 0.0f;
    const int g = t / PP;
    const int i = t - g * PP;
    const int batch = blockIdx.x * BPB + g;
    const bool active = (t < BPB * PP) && (batch < BB);
    float fi = 0.f, ar = 0.f, ai = 0.f;
    if (active) {
        int node = batch * PP + i;
        fi = features[node];
        float2 an = ((const float2*)angles)[node];
        ar = an.x; ai = an.y;
        float inv = 1.0f / (ar*ar + ai*ai);
        s_node[t] = make_float4(fi, ar*inv, ai*inv, 0.f);
    }
    __syncthreads();

    float sa[HN], ssa[HN];
#pragma unroll
    for (int c = 0; c < HN; c++) { sa[c] = 0.f; ssa[c] = 0.f; }

    if (active) {
        float tt[HN], Afj[HN], pc[HN], qc[HN];
#pragma unroll
        for (int c = 0; c < HN; c++) {
            float w0 = __ldg(&W1[c*5+0]), w1 = __ldg(&W1[c*5+1]), w2 = __ldg(&W1[c*5+2]);
            float w3 = __ldg(&W1[c*5+3]), w4 = __ldg(&W1[c*5+4]);
            Afj[c] = w1 + w2;
            tt[c]  = fmaf(w0 - w2, fi, __ldg(&b1[c]));
            pc[c]  = w3*ar + w4*ai;
            qc[c]  = w3*ai - w4*ar;
        }
        const int base = g * PP;
#pragma unroll 5
        for (int j = 0; j < PP; j++) {
            float4 nj = s_node[base + j];
#pragma unroll
            for (int c = 0; c < HN; c++) {
                float a = fmaf(Afj[c], nj.x, tt[c]);
                a = fmaf(pc[c], nj.y, a);
                a = fmaf(qc[c], nj.z, a);
                sa[c] += a;
                ssa[c] = fmaf(a, a, ssa[c]);
            }
        }
    }
#pragma unroll
    for (int c = 0; c < HN; c++) {
#pragma unroll
        for (int o = 16; o > 0; o >>= 1) {
            sa[c]  += __shfl_down_sync(0xffffffffu, sa[c],  o);
            ssa[c] += __shfl_down_sync(0xffffffffu, ssa[c], o);
        }
    }
    if ((t & 31) == 0) {
#pragma unroll
        for (int c = 0; c < HN; c++) {
            atomicAdd(&s_blk[c],      sa[c]);
            atomicAdd(&s_blk[HN + c], ssa[c]);
        }
    }
    __syncthreads();
    if (t < 10) atomicAdd(&g_acc1[t], s_blk[t]);
}

// ---------------- finalize 1: fold BN1 into layer-1 coefficients ----------------
__global__ void k_fin1(const float* __restrict__ W1, const float* __restrict__ b1,
                       const float* __restrict__ g1, const float* __restrict__ bt1)
{
    int c = threadIdx.x;
    if (c < HN) {
        const float invE = 1.0f / NEDGEF;
        float mean = g_acc1[c] * invE;
        float var  = g_acc1[5 + c] * invE - mean * mean;
        float s1 = g1[c] * rsqrtf(var + EPSBN);
        float o1 = bt1[c] - mean * s1;
        float w0 = W1[c*5+0], w1 = W1[c*5+1], w2 = W1[c*5+2], w3 = W1[c*5+3], w4 = W1[c*5+4];
        g_F1[c]      = s1 * (w0 - w2);        // FAfi
        g_F1[5 + c]  = fmaf(s1, b1[c], o1);   // Fb1
        g_F1[10 + c] = s1 * (w1 + w2);        // FAfj
        g_F1[15 + c] = s1 * w3;               // FW13
        g_F1[20 + c] = s1 * w4;               // FW14
    }
}

// ---------------- pass 2: h1 moments (layer-2 stats factor through them) ----------------
__global__ __launch_bounds__(TPB) void k_pass2(
    const float* __restrict__ features, const float* __restrict__ angles)
{
    __shared__ float4 s_node[BPB * PP];
    __shared__ float s_blk[20];
    const int t = threadIdx.x;
    if (t < 20) s_blk[t] = 0.0f;
    const int g = t / PP;
    const int i = t - g * PP;
    const int batch = blockIdx.x * BPB + g;
    const bool active = (t < BPB * PP) && (batch < BB);
    float fi = 0.f, ar = 0.f, ai = 0.f;
    if (active) {
        int node = batch * PP + i;
        fi = features[node];
        float2 an = ((const float2*)angles)[node];
        ar = an.x; ai = an.y;
        float inv = 1.0f / (ar*ar + ai*ai);
        s_node[t] = make_float4(fi, ar*inv, ai*inv, 0.f);
    }
    __syncthreads();

    float m1a[HN], M2a[15];
#pragma unroll
    for (int c = 0; c < HN; c++) m1a[c] = 0.f;
#pragma unroll
    for (int c = 0; c < 15; c++) M2a[c] = 0.f;

    if (active) {
        float th[HN], Afj[HN], pc[HN], qc[HN];
#pragma unroll
        for (int c = 0; c < HN; c++) {
            float F0 = g_F1[c], Fb = g_F1[5+c], F2 = g_F1[10+c], F3 = g_F1[15+c], F4 = g_F1[20+c];
            Afj[c] = F2;
            th[c]  = fmaf(F0, fi, Fb);
            pc[c]  = F3*ar + F4*ai;
            qc[c]  = F3*ai - F4*ar;
        }
        const int base = g * PP;
#pragma unroll 2
        for (int j = 0; j < PP; j++) {
            float4 nj = s_node[base + j];
            float h1[HN];
#pragma unroll
            for (int c = 0; c < HN; c++) {
                float a = fmaf(Afj[c], nj.x, th[c]);
                a = fmaf(pc[c], nj.y, a);
                a = fmaf(qc[c], nj.z, a);
                h1[c] = fmaxf(a, 0.01f * a);    // leaky relu
                m1a[c] += h1[c];
            }
            int idx = 0;
#pragma unroll
            for (int a2 = 0; a2 < HN; a2++)
#pragma unroll
                for (int b2 = a2; b2 < HN; b2++) {
                    M2a[idx] = fmaf(h1[a2], h1[b2], M2a[idx]);
                    idx++;
                }
        }
    }
    // reduce 20 values
#pragma unroll
    for (int c = 0; c < HN; c++)
#pragma unroll
        for (int o = 16; o > 0; o >>= 1)
            m1a[c] += __shfl_down_sync(0xffffffffu, m1a[c], o);
#pragma unroll
    for (int c = 0; c < 15; c++)
#pragma unroll
        for (int o = 16; o > 0; o >>= 1)
            M2a[c] += __shfl_down_sync(0xffffffffu, M2a[c], o);
    if ((t & 31) == 0) {
#pragma unroll
        for (int c = 0; c < HN; c++) atomicAdd(&s_blk[c], m1a[c]);
#pragma unroll
        for (int c = 0; c < 15; c++) atomicAdd(&s_blk[HN + c], M2a[c]);
    }
    __syncthreads();
    if (t < 20) atomicAdd(&g_acc2[t], s_blk[t]);
}

// ---------------- finalize 2: analytic layer-2 stats, fold BN2 into W2 ----------------
__global__ void k_fin2(const float* __restrict__ W2, const float* __restrict__ b2,
                       const float* __restrict__ g2, const float* __restrict__ bt2)
{
    int c = threadIdx.x;
    if (c < HN) {
        const float invE = 1.0f / NEDGEF;
        float w[HN], m1[HN];
#pragma unroll
        for (int k = 0; k < HN; k++) { w[k] = W2[c*5+k]; m1[k] = g_acc2[k] * invE; }
        float Sm = 0.f;
#pragma unroll
        for (int k = 0; k < HN; k++) Sm = fmaf(w[k], m1[k], Sm);
        float Sq = 0.f;
        int idx = 0;
#pragma unroll
        for (int a = 0; a < HN; a++)
#pragma unroll
            for (int b = a; b < HN; b++) {
                float m = g_acc2[5 + idx] * invE;
                float term = w[a] * w[b] * m;
                Sq += (a == b) ? term : 2.0f * term;
                idx++;
            }
        float bc   = b2[c];
        float mean = Sm + bc;
        float ex2  = Sq + bc * (2.0f * Sm + bc);
        float var  = ex2 - mean * mean;
        float s2 = g2[c] * rsqrtf(var + EPSBN);
        float o2 = bt2[c] - mean * s2;
#pragma unroll
        for (int k = 0; k < HN; k++) g_W2f[c*5+k] = s2 * w[k];
        g_b2f[c] = fmaf(s2, bc, o2);
    }
}

// ---------------- pass 3: full forward + aggregation + output ----------------
__global__ __launch_bounds__(TPB) void k_pass3(
    const float* __restrict__ pt, const float* __restrict__ features,
    const float* __restrict__ angles, const float* __restrict__ W3,
    const float* __restrict__ b3, float* __restrict__ out)
{
    __shared__ float4 s_node[BPB * PP];
    const int t = threadIdx.x;
    const int g = t / PP;
    const int i = t - g * PP;
    const int batch = blockIdx.x * BPB + g;
    const bool active = (t < BPB * PP) && (batch < BB);
    float fi = 0.f, ar = 0.f, ai = 0.f;
    int node = 0;
    if (active) {
        node = batch * PP + i;
        fi = features[node];
        float2 an = ((const float2*)angles)[node];
        ar = an.x; ai = an.y;
        float inv = 1.0f / (ar*ar + ai*ai);
        s_node[t] = make_float4(fi, ar*inv, ai*inv, 0.f);
    }
    __syncthreads();
    if (!active) return;

    float th[HN], Afj[HN], pc[HN], qc[HN];
#pragma unroll
    for (int c = 0; c < HN; c++) {
        float F0 = g_F1[c], Fb = g_F1[5+c], F2 = g_F1[10+c], F3 = g_F1[15+c], F4 = g_F1[20+c];
        Afj[c] = F2;
        th[c]  = fmaf(F0, fi, Fb);
        pc[c]  = F3*ar + F4*ai;
        qc[c]  = F3*ai - F4*ar;
    }
    float W2f[25], b2f[HN];
#pragma unroll
    for (int c = 0; c < 25; c++) W2f[c] = g_W2f[c];
#pragma unroll
    for (int c = 0; c < HN; c++) b2f[c] = g_b2f[c];

    float Sh2[HN];
#pragma unroll
    for (int c = 0; c < HN; c++) Sh2[c] = 0.f;

    const int base = g * PP;
#pragma unroll 2
    for (int j = 0; j < PP; j++) {
        float4 nj = s_node[base + j];
        float h1[HN];
#pragma unroll
        for (int c = 0; c < HN; c++) {
            float a = fmaf(Afj[c], nj.x, th[c]);
            a = fmaf(pc[c], nj.y, a);
            a = fmaf(qc[c], nj.z, a);
            h1[c] = fmaxf(a, 0.01f * a);
        }
#pragma unroll
        for (int c = 0; c < HN; c++) {
            float a2 = b2f[c];
#pragma unroll
            for (int k = 0; k < HN; k++) a2 = fmaf(W2f[c*5+k], h1[k], a2);
            float h2 = fmaxf(a2, 0.01f * a2);
            Sh2[c] += h2;
        }
    }
    // layer 3 applied once to the summed h2 (linear => commutes with sum)
    float sn[HN];
#pragma unroll
    for (int c = 0; c < HN; c++) sn[c] = Sh2[c] * (1.0f / (float)PP);
    float m[HN];
#pragma unroll
    for (int kk = 0; kk < HN; kk++) {
        float acc = __ldg(&b3[kk]);
#pragma unroll
        for (int k = 0; k < HN; k++) acc = fmaf(__ldg(&W3[kk*5+k]), sn[k], acc);
        m[kk] = acc;
    }
    float si, cs;
    sincosf(TWO_PI * m[4], &si, &cs);
    float* o = out + (size_t)node * 7;
    o[0] = pt[node];
    o[1] = m[0];
    o[2] = m[1];
    o[3] = m[2];
    o[4] = m[3];
    o[5] = cs * ar - si * ai;
    o[6] = cs * ai + si * ar;
}

extern "C" void kernel_launch(void* const* d_in, const int* in_sizes, int n_in,
                              void* d_out, int out_size)
{
    const float* pt       = (const float*)d_in[0];
    const float* features = (const float*)d_in[1];
    const float* angles   = (const float*)d_in[2];
    const float* W1       = (const float*)d_in[3];
    const float* b1       = (const float*)d_in[4];
    const float* g1       = (const float*)d_in[5];
    const float* bt1      = (const float*)d_in[6];
    const float* W2       = (const float*)d_in[7];
    const float* b2       = (const float*)d_in[8];
    const float* g2       = (const float*)d_in[9];
    const float* bt2      = (const float*)d_in[10];
    const float* W3       = (const float*)d_in[11];
    const float* b3       = (const float*)d_in[12];
    // d_in[13] = edge_index: structure is analytic (dense per-batch clique,
    // dst-major meshgrid), so it is not needed.
    float* out = (float*)d_out;

    k_init<<<1, 32>>>();
    k_pass1<<<NBLK, TPB>>>(features, angles, W1, b1);
    k_fin1<<<1, 32>>>(W1, b1, g1, bt1);
    k_pass2<<<NBLK, TPB>>>(features, angles);
    k_fin2<<<1, 32>>>(W2, b2, g2, bt2);
    k_pass3<<<NBLK, TPB>>>(pt, features, angles, W3, b3, out);
}

// round 4
// speedup vs baseline: 1.0059x; 1.0051x over previous
#include <cuda_runtime.h>
#include <math.h>

#define HN 5
#define PP 50
#define BB 2048
#define NTOT (BB*PP)
#define NEDGEF 5120000.0f
#define EPSBN 1e-5f
#define BPB 5            // batches per block
#define TPB 256          // 250 active threads (one per dst node)
#define NBLK ((BB + BPB - 1) / BPB)
#define TWO_PI 6.283185307179586f

// ---- scratch (no allocations allowed: __device__ globals) ----
__device__ float g_acc1[10];   // sum(a1[c]), sum(a1[c]^2)
__device__ float g_acc2[20];   // sum(h1[c]), sum(h1[a]*h1[b]) upper-tri (15)
__device__ float g_F1[25];     // folded layer1: FAfi, Fb1, FAfj, FW13, FW14 (5 each)
__device__ float g_W2f[25];    // BN2-folded W2
__device__ float g_b2f[HN];    // BN2-folded b2

__global__ void k_init() {
    int t = threadIdx.x;
    if (t < 10) g_acc1[t] = 0.0f;
    if (t < 20) g_acc2[t] = 0.0f;
}

// ---------------- pass 1: stats of a1 = mlp_in @ W1^T + b1 over all edges ----------------
__global__ __launch_bounds__(TPB) void k_pass1(
    const float* __restrict__ features, const float* __restrict__ angles,
    const float* __restrict__ W1, const float* __restrict__ b1)
{
    __shared__ float4 s_node[BPB * PP];  // {f, u, v, -} per node
    __shared__ float s_blk[10];
    const int t = threadIdx.x;
    if (t < 10) s_blk[t] = 0.0f;
    const int g = t / PP;
    const int i = t - g * PP;
    const int batch = blockIdx.x * BPB + g;
    const bool active = (t < BPB * PP) && (batch < BB);
    float fi = 0.f, ar = 0.f, ai = 0.f;
    if (active) {
        int node = batch * PP + i;
        fi = features[node];
        float2 an = ((const float2*)angles)[node];
        ar = an.x; ai = an.y;
        float inv = 1.0f / (ar*ar + ai*ai);
        s_node[t] = make_float4(fi, ar*inv, ai*inv, 0.f);
    }
    __syncthreads();

    float sa[HN], ssa[HN];
#pragma unroll
    for (int c = 0; c < HN; c++) { sa[c] = 0.f; ssa[c] = 0.f; }

    if (active) {
        float tt[HN], Afj[HN], pc[HN], qc[HN];
#pragma unroll
        for (int c = 0; c < HN; c++) {
            float w0 = __ldg(&W1[c*5+0]), w1 = __ldg(&W1[c*5+1]), w2 = __ldg(&W1[c*5+2]);
            float w3 = __ldg(&W1[c*5+3]), w4 = __ldg(&W1[c*5+4]);
            Afj[c] = w1 + w2;
            tt[c]  = fmaf(w0 - w2, fi, __ldg(&b1[c]));
            pc[c]  = w3*ar + w4*ai;
            qc[c]  = w3*ai - w4*ar;
        }
        const int base = g * PP;
#pragma unroll 5
        for (int j = 0; j < PP; j++) {
            float4 nj = s_node[base + j];
#pragma unroll
            for (int c = 0; c < HN; c++) {
                float a = fmaf(Afj[c], nj.x, tt[c]);
                a = fmaf(pc[c], nj.y, a);
                a = fmaf(qc[c], nj.z, a);
                sa[c] += a;
                ssa[c] = fmaf(a, a, ssa[c]);
            }
        }
    }
#pragma unroll
    for (int c = 0; c < HN; c++) {
#pragma unroll
        for (int o = 16; o > 0; o >>= 1) {
            sa[c]  += __shfl_down_sync(0xffffffffu, sa[c],  o);
            ssa[c] += __shfl_down_sync(0xffffffffu, ssa[c], o);
        }
    }
    if ((t & 31) == 0) {
#pragma unroll
        for (int c = 0; c < HN; c++) {
            atomicAdd(&s_blk[c],      sa[c]);
            atomicAdd(&s_blk[HN + c], ssa[c]);
        }
    }
    __syncthreads();
    if (t < 10) atomicAdd(&g_acc1[t], s_blk[t]);
}

// ---------------- finalize 1: fold BN1 into layer-1 coefficients ----------------
__global__ void k_fin1(const float* __restrict__ W1, const float* __restrict__ b1,
                       const float* __restrict__ g1, const float* __restrict__ bt1)
{
    int c = threadIdx.x;
    if (c < HN) {
        const float invE = 1.0f / NEDGEF;
        float mean = g_acc1[c] * invE;
        float var  = g_acc1[5 + c] * invE - mean * mean;
        float s1 = g1[c] * rsqrtf(var + EPSBN);
        float o1 = bt1[c] - mean * s1;
        float w0 = W1[c*5+0], w1 = W1[c*5+1], w2 = W1[c*5+2], w3 = W1[c*5+3], w4 = W1[c*5+4];
        g_F1[c]      = s1 * (w0 - w2);        // FAfi
        g_F1[5 + c]  = fmaf(s1, b1[c], o1);   // Fb1
        g_F1[10 + c] = s1 * (w1 + w2);        // FAfj
        g_F1[15 + c] = s1 * w3;               // FW13
        g_F1[20 + c] = s1 * w4;               // FW14
    }
}

// ---------------- pass 2: h1 moments (layer-2 stats factor through them) ----------------
__global__ __launch_bounds__(TPB) void k_pass2(
    const float* __restrict__ features, const float* __restrict__ angles)
{
    __shared__ float4 s_node[BPB * PP];
    __shared__ float s_blk[20];
    const int t = threadIdx.x;
    if (t < 20) s_blk[t] = 0.0f;
    const int g = t / PP;
    const int i = t - g * PP;
    const int batch = blockIdx.x * BPB + g;
    const bool active = (t < BPB * PP) && (batch < BB);
    float fi = 0.f, ar = 0.f, ai = 0.f;
    if (active) {
        int node = batch * PP + i;
        fi = features[node];
        float2 an = ((const float2*)angles)[node];
        ar = an.x; ai = an.y;
        float inv = 1.0f / (ar*ar + ai*ai);
        s_node[t] = make_float4(fi, ar*inv, ai*inv, 0.f);
    }
    __syncthreads();

    float m1a[HN], M2a[15];
#pragma unroll
    for (int c = 0; c < HN; c++) m1a[c] = 0.f;
#pragma unroll
    for (int c = 0; c < 15; c++) M2a[c] = 0.f;

    if (active) {
        float th[HN], Afj[HN], pc[HN], qc[HN];
#pragma unroll
        for (int c = 0; c < HN; c++) {
            float F0 = g_F1[c], Fb = g_F1[5+c], F2 = g_F1[10+c], F3 = g_F1[15+c], F4 = g_F1[20+c];
            Afj[c] = F2;
            th[c]  = fmaf(F0, fi, Fb);
            pc[c]  = F3*ar + F4*ai;
            qc[c]  = F3*ai - F4*ar;
        }
        const int base = g * PP;
#pragma unroll 2
        for (int j = 0; j < PP; j++) {
            float4 nj = s_node[base + j];
            float h1[HN];
#pragma unroll
            for (int c = 0; c < HN; c++) {
                float a = fmaf(Afj[c], nj.x, th[c]);
                a = fmaf(pc[c], nj.y, a);
                a = fmaf(qc[c], nj.z, a);
                h1[c] = fmaxf(a, 0.01f * a);    // leaky relu
                m1a[c] += h1[c];
            }
            int idx = 0;
#pragma unroll
            for (int a2 = 0; a2 < HN; a2++)
#pragma unroll
                for (int b2 = a2; b2 < HN; b2++) {
                    M2a[idx] = fmaf(h1[a2], h1[b2], M2a[idx]);
                    idx++;
                }
        }
    }
    // reduce 20 values
#pragma unroll
    for (int c = 0; c < HN; c++)
#pragma unroll
        for (int o = 16; o > 0; o >>= 1)
            m1a[c] += __shfl_down_sync(0xffffffffu, m1a[c], o);
#pragma unroll
    for (int c = 0; c < 15; c++)
#pragma unroll
        for (int o = 16; o > 0; o >>= 1)
            M2a[c] += __shfl_down_sync(0xffffffffu, M2a[c], o);
    if ((t & 31) == 0) {
#pragma unroll
        for (int c = 0; c < HN; c++) atomicAdd(&s_blk[c], m1a[c]);
#pragma unroll
        for (int c = 0; c < 15; c++) atomicAdd(&s_blk[HN + c], M2a[c]);
    }
    __syncthreads();
    if (t < 20) atomicAdd(&g_acc2[t], s_blk[t]);
}

// ---------------- finalize 2: analytic layer-2 stats, fold BN2 into W2 ----------------
__global__ void k_fin2(const float* __restrict__ W2, const float* __restrict__ b2,
                       const float* __restrict__ g2, const float* __restrict__ bt2)
{
    int c = threadIdx.x;
    if (c < HN) {
        const float invE = 1.0f / NEDGEF;
        float w[HN], m1[HN];
#pragma unroll
        for (int k = 0; k < HN; k++) { w[k] = W2[c*5+k]; m1[k] = g_acc2[k] * invE; }
        float Sm = 0.f;
#pragma unroll
        for (int k = 0; k < HN; k++) Sm = fmaf(w[k], m1[k], Sm);
        float Sq = 0.f;
        int idx = 0;
#pragma unroll
        for (int a = 0; a < HN; a++)
#pragma unroll
            for (int b = a; b < HN; b++) {
                float m = g_acc2[5 + idx] * invE;
                float term = w[a] * w[b] * m;
                Sq += (a == b) ? term : 2.0f * term;
                idx++;
            }
        float bc   = b2[c];
        float mean = Sm + bc;
        float ex2  = Sq + bc * (2.0f * Sm + bc);
        float var  = ex2 - mean * mean;
        float s2 = g2[c] * rsqrtf(var + EPSBN);
        float o2 = bt2[c] - mean * s2;
#pragma unroll
        for (int k = 0; k < HN; k++) g_W2f[c*5+k] = s2 * w[k];
        g_b2f[c] = fmaf(s2, bc, o2);
    }
}

// ---------------- pass 3: full forward + aggregation + output ----------------
__global__ __launch_bounds__(TPB) void k_pass3(
    const float* __restrict__ pt, const float* __restrict__ features,
    const float* __restrict__ angles, const float* __restrict__ W3,
    const float* __restrict__ b3, float* __restrict__ out)
{
    __shared__ float4 s_node[BPB * PP];
    const int t = threadIdx.x;
    const int g = t / PP;
    const int i = t - g * PP;
    const int batch = blockIdx.x * BPB + g;
    const bool active = (t < BPB * PP) && (batch < BB);
    float fi = 0.f, ar = 0.f, ai = 0.f;
    int node = 0;
    if (active) {
        node = batch * PP + i;
        fi = features[node];
        float2 an = ((const float2*)angles)[node];
        ar = an.x; ai = an.y;
        float inv = 1.0f / (ar*ar + ai*ai);
        s_node[t] = make_float4(fi, ar*inv, ai*inv, 0.f);
    }
    __syncthreads();
    if (!active) return;

    float th[HN], Afj[HN], pc[HN], qc[HN];
#pragma unroll
    for (int c = 0; c < HN; c++) {
        float F0 = g_F1[c], Fb = g_F1[5+c], F2 = g_F1[10+c], F3 = g_F1[15+c], F4 = g_F1[20+c];
        Afj[c] = F2;
        th[c]  = fmaf(F0, fi, Fb);
        pc[c]  = F3*ar + F4*ai;
        qc[c]  = F3*ai - F4*ar;
    }
    float W2f[25], b2f[HN];
#pragma unroll
    for (int c = 0; c < 25; c++) W2f[c] = g_W2f[c];
#pragma unroll
    for (int c = 0; c < HN; c++) b2f[c] = g_b2f[c];

    float Sh2[HN];
#pragma unroll
    for (int c = 0; c < HN; c++) Sh2[c] = 0.f;

    const int base = g * PP;
#pragma unroll 2
    for (int j = 0; j < PP; j++) {
        float4 nj = s_node[base + j];
        float h1[HN];
#pragma unroll
        for (int c = 0; c < HN; c++) {
            float a = fmaf(Afj[c], nj.x, th[c]);
            a = fmaf(pc[c], nj.y, a);
            a = fmaf(qc[c], nj.z, a);
            h1[c] = fmaxf(a, 0.01f * a);
        }
#pragma unroll
        for (int c = 0; c < HN; c++) {
            float a2 = b2f[c];
#pragma unroll
            for (int k = 0; k < HN; k++) a2 = fmaf(W2f[c*5+k], h1[k], a2);
            float h2 = fmaxf(a2, 0.01f * a2);
            Sh2[c] += h2;
        }
    }
    // layer 3 applied once to the summed h2 (linear => commutes with sum)
    float sn[HN];
#pragma unroll
    for (int c = 0; c < HN; c++) sn[c] = Sh2[c] * (1.0f / (float)PP);
    float m[HN];
#pragma unroll
    for (int kk = 0; kk < HN; kk++) {
        float acc = __ldg(&b3[kk]);
#pragma unroll
        for (int k = 0; k < HN; k++) acc = fmaf(__ldg(&W3[kk*5+k]), sn[k], acc);
        m[kk] = acc;
    }
    float si, cs;
    sincosf(TWO_PI * m[4], &si, &cs);
    float* o = out + (size_t)node * 7;
    o[0] = pt[node];
    o[1] = m[0];
    o[2] = m[1];
    o[3] = m[2];
    o[4] = m[3];
    o[5] = cs * ar - si * ai;
    o[6] = cs * ai + si * ar;
}

extern "C" void kernel_launch(void* const* d_in, const int* in_sizes, int n_in,
                              void* d_out, int out_size)
{
    const float* pt       = (const float*)d_in[0];
    const float* features = (const float*)d_in[1];
    const float* angles   = (const float*)d_in[2];
    const float* W1       = (const float*)d_in[3];
    const float* b1       = (const float*)d_in[4];
    const float* g1       = (const float*)d_in[5];
    const float* bt1      = (const float*)d_in[6];
    const float* W2       = (const float*)d_in[7];
    const float* b2       = (const float*)d_in[8];
    const float* g2       = (const float*)d_in[9];
    const float* bt2      = (const float*)d_in[10];
    const float* W3       = (const float*)d_in[11];
    const float* b3       = (const float*)d_in[12];
    // d_in[13] = edge_index: structure is analytic (dense per-batch clique,
    // dst-major meshgrid), so it is not needed.
    float* out = (float*)d_out;

    k_init<<<1, 32>>>();
    k_pass1<<<NBLK, TPB>>>(features, angles, W1, b1);
    k_fin1<<<1, 32>>>(W1, b1, g1, bt1);
    k_pass2<<<NBLK, TPB>>>(features, angles);
    k_fin2<<<1, 32>>>(W2, b2, g2, bt2);
    k_pass3<<<NBLK, TPB>>>(pt, features, angles, W3, b3, out);
}